// round 1
// baseline (speedup 1.0000x reference)
#include <cuda_runtime.h>
#include <cstdint>

// Problem constants: B=1024, F=16, D=64, P=F*(F-1)/2=120
// out[b,p,k] = sum_{a,c} x[b,ii[p],a] * x[b,jj[p],c] * W[p,k,a*64+c] + bias[p,k]
// Factored: S_a[b,k] = sum_c xj[b,c]*W[p,k,a*64+c];  out += xi[b,a]*S_a[b,k]

#define BDIM 1024
#define FDIM 16
#define DDIM 64
#define PDIM 120
#define WS_STRIDE 68   // padded row stride for ws[c][k] (16B aligned, low-conflict)

__global__ __launch_bounds__(256, 2)
void fused_pairwise_kernel(const float* __restrict__ x,
                           const float* __restrict__ W,
                           const float* __restrict__ bias,
                           float* __restrict__ out)
{
    extern __shared__ float smem[];
    float* xi_s = smem;                    // [128][64]
    float* xj_s = smem + 128 * 64;         // [128][64]
    float* ws0  = smem + 2 * 128 * 64;     // [2][64][WS_STRIDE]  (ws[c][k] transposed)

    const int tid = threadIdx.x;
    const int tx  = tid & 15;              // 0..15 -> k columns tx*4..tx*4+3
    const int ty  = tid >> 4;              // 0..15 -> b rows ty*8..ty*8+7
    const int p   = blockIdx.x >> 3;       // p-major ordering: 8 b-tiles of same p adjacent (L2 reuse of W_p)
    const int b0  = (blockIdx.x & 7) << 7; // b-tile origin

    // pair (fi, fj) from p: triu_indices(16, k=1), row-major
    int fi = 0, rem = p;
    while (rem >= 15 - fi) { rem -= 15 - fi; ++fi; }
    const int fj = fi + 1 + rem;

    // ---- load xi / xj tiles: 128 rows x 64 floats each, fully coalesced float4 ----
    {
        #pragma unroll
        for (int it = 0; it < 8; ++it) {
            const int row = ty + it * 16;
            const float* xb = x + ((size_t)(b0 + row) * FDIM) * DDIM;
            *(float4*)&xi_s[row * 64 + tx * 4] = *(const float4*)(xb + fi * 64 + tx * 4);
            *(float4*)&xj_s[row * 64 + tx * 4] = *(const float4*)(xb + fj * 64 + tx * 4);
        }
    }

    const float* Wp = W + (size_t)p * (64 * 4096);
    // W tile loader: thread (tx=wc4, ty=wk) loads rows k = wk, wk+16, wk+32, wk+48,
    // columns c = wc4*4..wc4*4+3 of the 64x64 a-slab. Coalesced 256B row segments.
    const int wc4 = tx;
    const int wk  = ty;

    float4 w0r, w1r, w2r, w3r;

    // prologue: LDG a=0, STS into buffer 0
    {
        const float* g = Wp + wc4 * 4;  // a = 0
        w0r = *(const float4*)(g + (wk +  0) * 4096);
        w1r = *(const float4*)(g + (wk + 16) * 4096);
        w2r = *(const float4*)(g + (wk + 32) * 4096);
        w3r = *(const float4*)(g + (wk + 48) * 4096);
    }
    {
        float* wb = ws0 + (wc4 * 4) * WS_STRIDE + wk;
        wb[0*WS_STRIDE +  0] = w0r.x; wb[1*WS_STRIDE +  0] = w0r.y; wb[2*WS_STRIDE +  0] = w0r.z; wb[3*WS_STRIDE +  0] = w0r.w;
        wb[0*WS_STRIDE + 16] = w1r.x; wb[1*WS_STRIDE + 16] = w1r.y; wb[2*WS_STRIDE + 16] = w1r.z; wb[3*WS_STRIDE + 16] = w1r.w;
        wb[0*WS_STRIDE + 32] = w2r.x; wb[1*WS_STRIDE + 32] = w2r.y; wb[2*WS_STRIDE + 32] = w2r.z; wb[3*WS_STRIDE + 32] = w2r.w;
        wb[0*WS_STRIDE + 48] = w3r.x; wb[1*WS_STRIDE + 48] = w3r.y; wb[2*WS_STRIDE + 48] = w3r.z; wb[3*WS_STRIDE + 48] = w3r.w;
    }
    __syncthreads();

    float acc[8][4];
    #pragma unroll
    for (int i = 0; i < 8; ++i)
        #pragma unroll
        for (int j = 0; j < 4; ++j) acc[i][j] = 0.0f;

    const int row0 = ty * 8;

    #pragma unroll 1
    for (int a = 0; a < 64; ++a) {
        const int buf = a & 1;

        // register-staged prefetch of next a-slab (overlaps the whole c-loop)
        if (a < 63) {
            const float* g = Wp + (a + 1) * 64 + wc4 * 4;
            w0r = *(const float4*)(g + (wk +  0) * 4096);
            w1r = *(const float4*)(g + (wk + 16) * 4096);
            w2r = *(const float4*)(g + (wk + 32) * 4096);
            w3r = *(const float4*)(g + (wk + 48) * 4096);
        }

        // S_a[b,k] = sum_c xj[b,c] * W[k, a*64+c]
        float S[8][4];
        #pragma unroll
        for (int i = 0; i < 8; ++i)
            #pragma unroll
            for (int j = 0; j < 4; ++j) S[i][j] = 0.0f;

        const float* wb = ws0 + buf * (64 * WS_STRIDE);

        #pragma unroll 4
        for (int c4 = 0; c4 < 16; ++c4) {
            const float* wr = wb + (c4 * 4) * WS_STRIDE + tx * 4;
            const float4 q0 = *(const float4*)(wr + 0 * WS_STRIDE);
            const float4 q1 = *(const float4*)(wr + 1 * WS_STRIDE);
            const float4 q2 = *(const float4*)(wr + 2 * WS_STRIDE);
            const float4 q3 = *(const float4*)(wr + 3 * WS_STRIDE);
            #pragma unroll
            for (int i = 0; i < 8; ++i) {
                const float4 xv = *(const float4*)&xj_s[(row0 + i) * 64 + c4 * 4];
                S[i][0] = fmaf(xv.x, q0.x, S[i][0]);
                S[i][0] = fmaf(xv.y, q1.x, S[i][0]);
                S[i][0] = fmaf(xv.z, q2.x, S[i][0]);
                S[i][0] = fmaf(xv.w, q3.x, S[i][0]);
                S[i][1] = fmaf(xv.x, q0.y, S[i][1]);
                S[i][1] = fmaf(xv.y, q1.y, S[i][1]);
                S[i][1] = fmaf(xv.z, q2.y, S[i][1]);
                S[i][1] = fmaf(xv.w, q3.y, S[i][1]);
                S[i][2] = fmaf(xv.x, q0.z, S[i][2]);
                S[i][2] = fmaf(xv.y, q1.z, S[i][2]);
                S[i][2] = fmaf(xv.z, q2.z, S[i][2]);
                S[i][2] = fmaf(xv.w, q3.z, S[i][2]);
                S[i][3] = fmaf(xv.x, q0.w, S[i][3]);
                S[i][3] = fmaf(xv.y, q1.w, S[i][3]);
                S[i][3] = fmaf(xv.z, q2.w, S[i][3]);
                S[i][3] = fmaf(xv.w, q3.w, S[i][3]);
            }
        }

        // out += xi[b,a] * S_a
        #pragma unroll
        for (int i = 0; i < 8; ++i) {
            const float xiv = xi_s[(row0 + i) * 64 + a];
            acc[i][0] = fmaf(xiv, S[i][0], acc[i][0]);
            acc[i][1] = fmaf(xiv, S[i][1], acc[i][1]);
            acc[i][2] = fmaf(xiv, S[i][2], acc[i][2]);
            acc[i][3] = fmaf(xiv, S[i][3], acc[i][3]);
        }

        // store next slab into the other buffer; single barrier per iteration
        if (a < 63) {
            float* wn = ws0 + (buf ^ 1) * (64 * WS_STRIDE) + (wc4 * 4) * WS_STRIDE + wk;
            wn[0*WS_STRIDE +  0] = w0r.x; wn[1*WS_STRIDE +  0] = w0r.y; wn[2*WS_STRIDE +  0] = w0r.z; wn[3*WS_STRIDE +  0] = w0r.w;
            wn[0*WS_STRIDE + 16] = w1r.x; wn[1*WS_STRIDE + 16] = w1r.y; wn[2*WS_STRIDE + 16] = w1r.z; wn[3*WS_STRIDE + 16] = w1r.w;
            wn[0*WS_STRIDE + 32] = w2r.x; wn[1*WS_STRIDE + 32] = w2r.y; wn[2*WS_STRIDE + 32] = w2r.z; wn[3*WS_STRIDE + 32] = w2r.w;
            wn[0*WS_STRIDE + 48] = w3r.x; wn[1*WS_STRIDE + 48] = w3r.y; wn[2*WS_STRIDE + 48] = w3r.z; wn[3*WS_STRIDE + 48] = w3r.w;
        }
        __syncthreads();
    }

    // epilogue: add bias, write out (coalesced float4)
    const float4 bv = *(const float4*)(bias + p * 64 + tx * 4);
    #pragma unroll
    for (int i = 0; i < 8; ++i) {
        float4 o;
        o.x = acc[i][0] + bv.x;
        o.y = acc[i][1] + bv.y;
        o.z = acc[i][2] + bv.z;
        o.w = acc[i][3] + bv.w;
        *(float4*)(out + (size_t)(b0 + row0 + i) * (PDIM * DDIM) + p * 64 + tx * 4) = o;
    }
}

extern "C" void kernel_launch(void* const* d_in, const int* in_sizes, int n_in,
                              void* d_out, int out_size)
{
    const float* x    = (const float*)d_in[0];   // (1024, 16, 64) f32
    const float* W    = (const float*)d_in[1];   // (120, 64, 4096) f32
    const float* bias = (const float*)d_in[2];   // (120, 64) f32
    float* out = (float*)d_out;                  // (1024, 120, 64) f32

    const int smem_bytes = (2 * 128 * 64 + 2 * 64 * WS_STRIDE) * (int)sizeof(float); // ~99.3 KB
    cudaFuncSetAttribute(fused_pairwise_kernel,
                         cudaFuncAttributeMaxDynamicSharedMemorySize, smem_bytes);

    // 120 p values x 8 b-tiles of 128 rows; p-major block order for L2 reuse of W_p
    fused_pairwise_kernel<<<PDIM * 8, 256, smem_bytes>>>(x, W, bias, out);
}

// round 3
// speedup vs baseline: 3.2142x; 3.2142x over previous
#include <cuda_runtime.h>
#include <cstdint>

// B=1024, F=16, D=64, P=120
// out[b,p,k] = sum_{a,c} xi[b,a]*xj[b,c]*W[p,k,a*64+c] + bias[p,k]
// Per (p, b-tile): C[128,64] = Z[128,4096] @ W_p[64,4096]^T via mma.sync tf32.
// Z built on-the-fly in registers; W staged through a 4-deep cp.async ring.

#define PDIM 120
#define OUT_ROW (PDIM * 64)

#define XST 68                       // xi/xj row stride (floats): 16B-aligned, conflict-free
#define WST 36                       // W stage row stride (floats): conflict-free B reads
#define OFF_XI 0
#define OFF_XJ (128 * XST)           // 8704
#define OFF_WS (OFF_XJ + 128 * XST)  // 17408
#define OFF_BIAS (OFF_WS + 4 * 64 * WST)  // 26624
#define SM_FLOATS (OFF_BIAS + 64)
#define SM_BYTES (SM_FLOATS * 4)     // 106752 B -> 2 CTAs/SM

__device__ __forceinline__ uint32_t smem_u32(const void* p) {
    uint32_t a;
    asm("{ .reg .u64 t; cvta.to.shared.u64 t, %1; cvt.u32.u64 %0, t; }" : "=r"(a) : "l"(p));
    return a;
}
__device__ __forceinline__ void cp16(uint32_t dst, const float* src) {
    asm volatile("cp.async.cg.shared.global [%0], [%1], 16;" :: "r"(dst), "l"(src));
}
__device__ __forceinline__ uint32_t tf32r(float f) {
    uint32_t r;
    asm("cvt.rna.tf32.f32 %0, %1;" : "=r"(r) : "f"(f));
    return r;
}
__device__ __forceinline__ void mma8(float* d,
                                     uint32_t a0, uint32_t a1, uint32_t a2, uint32_t a3,
                                     uint32_t b0, uint32_t b1) {
    asm volatile(
        "mma.sync.aligned.m16n8k8.row.col.f32.tf32.tf32.f32 "
        "{%0,%1,%2,%3},{%4,%5,%6,%7},{%8,%9},{%0,%1,%2,%3};"
        : "+f"(d[0]), "+f"(d[1]), "+f"(d[2]), "+f"(d[3])
        : "r"(a0), "r"(a1), "r"(a2), "r"(a3), "r"(b0), "r"(b1));
}

__global__ __launch_bounds__(256, 2)
void op_mma_kernel(const float* __restrict__ x,
                   const float* __restrict__ W,
                   const float* __restrict__ bias,
                   float* __restrict__ out)
{
    extern __shared__ __align__(16) float sm[];
    const int tid  = threadIdx.x;
    const int lane = tid & 31;
    const int wid  = tid >> 5;
    const int warpM = wid & 3;    // 4 warps x 32 rows = 128 M
    const int warpN = wid >> 2;   // 2 warps x 32 cols = 64 N
    const int p  = blockIdx.x >> 3;
    const int b0 = (blockIdx.x & 7) << 7;

    // pair (fi, fj) from triu_indices(16, k=1)
    int fi = 0, rem = p;
    while (rem >= 15 - fi) { rem -= 15 - fi; ++fi; }
    const int fj = fi + 1 + rem;

    // ---- one-time fills: xi/xj tiles (coalesced float4), bias ----
    {
        const int c4 = (tid & 15) * 4, r0 = tid >> 4;
        #pragma unroll
        for (int it = 0; it < 8; ++it) {
            const int row = r0 + it * 16;
            const float* g = x + (size_t)(b0 + row) * 1024;
            *(float4*)&sm[OFF_XI + row * XST + c4] = *(const float4*)(g + fi * 64 + c4);
            *(float4*)&sm[OFF_XJ + row * XST + c4] = *(const float4*)(g + fj * 64 + c4);
        }
    }
    if (tid < 16)
        *(float4*)&sm[OFF_BIAS + tid * 4] = *(const float4*)(bias + p * 64 + tid * 4);

    const float* Wp = W + (size_t)p * (64 * 4096);
    const uint32_t sb = smem_u32(sm);

    // cp.async mapping: thread covers row n = tid>>2, 2x16B at quads wq, wq+4
    const int wn = tid >> 2, wq = tid & 3;
    const float* wg = Wp + (size_t)wn * 4096 + wq * 4;
    const uint32_t wsm = sb + (uint32_t)(OFF_WS + wn * WST + wq * 4) * 4;

    // prologue: stages 0..2
    #pragma unroll
    for (int st = 0; st < 3; ++st) {
        cp16(wsm + (uint32_t)st * (64 * WST * 4), wg + st * 32);
        cp16(wsm + (uint32_t)st * (64 * WST * 4) + 64, wg + st * 32 + 16);
        asm volatile("cp.async.commit_group;" ::: "memory");
    }

    float acc[2][4][4];
    #pragma unroll
    for (int mt = 0; mt < 2; ++mt)
        #pragma unroll
        for (int nt = 0; nt < 4; ++nt)
            #pragma unroll
            for (int q = 0; q < 4; ++q) acc[mt][nt][q] = 0.0f;

    const int rb = warpM * 32 + (lane >> 2);   // A row base (group row)
    const int nb = warpN * 32 + (lane >> 2);   // B col base
    const int kq = lane & 3;

    const float* xi_b = sm + OFF_XI + rb * XST;
    const float* xj_b = sm + OFF_XJ + rb * XST;

    // ---- main loop: 128 chunks of K=32 ----
    #pragma unroll 1
    for (int s = 0; s < 128; ++s) {
        asm volatile("cp.async.wait_group 2;" ::: "memory");
        __syncthreads();

        // issue stage s+3 (into buf (s+3)&3, freed at the sync above)
        if (s < 125) {
            const int st = s + 3;
            cp16(wsm + (uint32_t)(st & 3) * (64 * WST * 4), wg + st * 32);
            cp16(wsm + (uint32_t)(st & 3) * (64 * WST * 4) + 64, wg + st * 32 + 16);
        }
        asm volatile("cp.async.commit_group;" ::: "memory");

        const float* ws = sm + OFF_WS + (s & 3) * (64 * WST);
        const int a  = s >> 1;            // chunk covers a single 'a' index
        const int ch = (s & 1) * 32;      // c offset within [0,64)

        float xiv[4];
        #pragma unroll
        for (int m = 0; m < 4; ++m) xiv[m] = xi_b[m * 8 * XST + a];

        #pragma unroll
        for (int t = 0; t < 4; ++t) {
            const int c0 = ch + t * 8 + kq;
            float xj0[4], xj1[4];
            #pragma unroll
            for (int m = 0; m < 4; ++m) {
                xj0[m] = xj_b[m * 8 * XST + c0];
                xj1[m] = xj_b[m * 8 * XST + c0 + 4];
            }
            // A fragments (Z values), rounded to tf32
            const uint32_t A00 = tf32r(xiv[0] * xj0[0]);
            const uint32_t A01 = tf32r(xiv[1] * xj0[1]);
            const uint32_t A02 = tf32r(xiv[0] * xj1[0]);
            const uint32_t A03 = tf32r(xiv[1] * xj1[1]);
            const uint32_t A10 = tf32r(xiv[2] * xj0[2]);
            const uint32_t A11 = tf32r(xiv[3] * xj0[3]);
            const uint32_t A12 = tf32r(xiv[2] * xj1[2]);
            const uint32_t A13 = tf32r(xiv[3] * xj1[3]);

            const int kk = t * 8 + kq;
            #pragma unroll
            for (int nt = 0; nt < 4; ++nt) {
                const float* wsr = ws + (nb + nt * 8) * WST;
                const uint32_t b0f = tf32r(wsr[kk]);
                const uint32_t b1f = tf32r(wsr[kk + 4]);
                mma8(acc[0][nt], A00, A01, A02, A03, b0f, b1f);
                mma8(acc[1][nt], A10, A11, A12, A13, b0f, b1f);
            }
        }
    }

    // ---- epilogue: bias + store (float2, 32B sectors fully used) ----
    const int colb = warpN * 32 + kq * 2;
    #pragma unroll
    for (int mt = 0; mt < 2; ++mt) {
        const int r_ = b0 + warpM * 32 + mt * 16 + (lane >> 2);
        float* o0 = out + (size_t)r_ * OUT_ROW + p * 64;
        float* o1 = out + (size_t)(r_ + 8) * OUT_ROW + p * 64;
        #pragma unroll
        for (int nt = 0; nt < 4; ++nt) {
            const int cl = colb + nt * 8;
            const float bz0 = sm[OFF_BIAS + cl];
            const float bz1 = sm[OFF_BIAS + cl + 1];
            float2 v0, v1;
            v0.x = acc[mt][nt][0] + bz0; v0.y = acc[mt][nt][1] + bz1;
            v1.x = acc[mt][nt][2] + bz0; v1.y = acc[mt][nt][3] + bz1;
            *(float2*)(o0 + cl) = v0;
            *(float2*)(o1 + cl) = v1;
        }
    }
}

extern "C" void kernel_launch(void* const* d_in, const int* in_sizes, int n_in,
                              void* d_out, int out_size)
{
    const float* x    = (const float*)d_in[0];   // (1024, 16, 64)
    const float* W    = (const float*)d_in[1];   // (120, 64, 4096)
    const float* bias = (const float*)d_in[2];   // (120, 64)
    float* out = (float*)d_out;                  // (1024, 120, 64)

    cudaFuncSetAttribute(op_mma_kernel,
                         cudaFuncAttributeMaxDynamicSharedMemorySize, SM_BYTES);
    // 120 p x 8 b-tiles; p-major for W_p L2 reuse across the 8 tiles
    op_mma_kernel<<<PDIM * 8, 256, SM_BYTES>>>(x, W, bias, out);
}

// round 4
// speedup vs baseline: 3.9817x; 1.2388x over previous
#include <cuda_runtime.h>
#include <cuda_fp16.h>
#include <cstdint>

// B=1024, F=16, D=64, P=120
// out[b,p,k] = sum_{a,c} xi[b,a]*xj[b,c]*W[p,k,a*64+c] + bias[p,k]
// Per (p, b-tile): C[128,64] = Z[128,4096] @ W_p[64,4096]^T via mma.m16n8k16.f16 (f32 acc).
// W pre-converted to fp16 once per launch (separate kernel, __device__ scratch).
// Z built on-the-fly in registers (f32 product, single rn rounding -> fp16).

#define PDIM 120
#define OUT_ROW (PDIM * 64)
#define WELEMS (120 * 64 * 4096)

__device__ __half d_Wh[WELEMS];   // 62.9 MB fp16 W scratch

// ---- SMEM layout ----
#define XST 68                          // xi/xj row stride (floats)
#define OFF_XI 0
#define OFF_XJ (128 * XST)              // 8704 floats
#define OFF_BIAS (OFF_XJ + 128 * XST)   // 17408 floats
#define OFF_WS_B ((OFF_BIAS + 64) * 4)  // 69888 bytes (16B aligned)
#define WROW 72                         // W stage row stride (halfs): conflict-free b32 reads
#define STAGE_B (64 * WROW * 2)         // 9216 bytes
#define SM_BYTES (OFF_WS_B + 4 * STAGE_B)  // 106752 -> 2 CTAs/SM

__device__ __forceinline__ uint32_t smem_u32(const void* p) {
    uint32_t a;
    asm("{ .reg .u64 t; cvta.to.shared.u64 t, %1; cvt.u32.u64 %0, t; }" : "=r"(a) : "l"(p));
    return a;
}
__device__ __forceinline__ void cp16(uint32_t dst, const void* src) {
    asm volatile("cp.async.cg.shared.global [%0], [%1], 16;" :: "r"(dst), "l"(src));
}
__device__ __forceinline__ void mma16(float* d,
                                      uint32_t a0, uint32_t a1, uint32_t a2, uint32_t a3,
                                      uint32_t b0, uint32_t b1) {
    asm volatile(
        "mma.sync.aligned.m16n8k16.row.col.f32.f16.f16.f32 "
        "{%0,%1,%2,%3},{%4,%5,%6,%7},{%8,%9},{%0,%1,%2,%3};"
        : "+f"(d[0]), "+f"(d[1]), "+f"(d[2]), "+f"(d[3])
        : "r"(a0), "r"(a1), "r"(a2), "r"(a3), "r"(b0), "r"(b1));
}

// ---- W fp32 -> fp16 convert: 31.46M elems, 4 per thread ----
__global__ __launch_bounds__(256)
void convert_W_kernel(const float* __restrict__ W)
{
    const size_t i4 = ((size_t)blockIdx.x * 256 + threadIdx.x) * 4;
    const float4 v = *(const float4*)(W + i4);
    __half2 h0 = __floats2half2_rn(v.x, v.y);
    __half2 h1 = __floats2half2_rn(v.z, v.w);
    uint2 u;
    u.x = *(uint32_t*)&h0;
    u.y = *(uint32_t*)&h1;
    *(uint2*)(&d_Wh[i4]) = u;
}

__global__ __launch_bounds__(256, 2)
void op_fp16_kernel(const float* __restrict__ x,
                    const float* __restrict__ bias,
                    float* __restrict__ out)
{
    extern __shared__ __align__(16) float sm[];
    const int tid  = threadIdx.x;
    const int lane = tid & 31;
    const int wid  = tid >> 5;
    const int warpM = wid & 3;    // 4 x 32 rows = 128 M
    const int warpN = wid >> 2;   // 2 x 32 cols = 64 N
    const int p  = blockIdx.x >> 3;
    const int b0 = (blockIdx.x & 7) << 7;

    // pair (fi, fj) from triu_indices(16, k=1)
    int fi = 0, rem = p;
    while (rem >= 15 - fi) { rem -= 15 - fi; ++fi; }
    const int fj = fi + 1 + rem;

    // ---- one-time fills: xi/xj tiles, bias ----
    {
        const int c4 = (tid & 15) * 4, r0 = tid >> 4;
        #pragma unroll
        for (int it = 0; it < 8; ++it) {
            const int row = r0 + it * 16;
            const float* g = x + (size_t)(b0 + row) * 1024;
            *(float4*)&sm[OFF_XI + row * XST + c4] = *(const float4*)(g + fi * 64 + c4);
            *(float4*)&sm[OFF_XJ + row * XST + c4] = *(const float4*)(g + fj * 64 + c4);
        }
    }
    if (tid < 16)
        *(float4*)&sm[OFF_BIAS + tid * 4] = *(const float4*)(bias + p * 64 + tid * 4);

    const __half* Wp = d_Wh + (size_t)p * (64 * 4096);
    const uint32_t sb = smem_u32(sm);
    const uint32_t wsb = sb + OFF_WS_B;

    // cp.async mapping: row wn = tid>>2 (0..63), two 16B quarters wq, wq+4
    const int wn = tid >> 2, wq = tid & 3;
    const __half* wg = Wp + (size_t)wn * 4096;
    const uint32_t wdst = wsb + (uint32_t)(wn * (WROW * 2));

    // prologue: stages 0..2
    #pragma unroll
    for (int st = 0; st < 3; ++st) {
        cp16(wdst + (uint32_t)st * STAGE_B + wq * 16, wg + st * 64 + wq * 8);
        cp16(wdst + (uint32_t)st * STAGE_B + (wq + 4) * 16, wg + st * 64 + (wq + 4) * 8);
        asm volatile("cp.async.commit_group;" ::: "memory");
    }

    float acc[2][4][4];
    #pragma unroll
    for (int mt = 0; mt < 2; ++mt)
        #pragma unroll
        for (int nt = 0; nt < 4; ++nt)
            #pragma unroll
            for (int q = 0; q < 4; ++q) acc[mt][nt][q] = 0.0f;

    const int rb = warpM * 32 + (lane >> 2);   // A row base (m=0)
    const int nb = warpN * 32 + (lane >> 2);   // B col base (nt=0)
    const int kq = lane & 3;

    const float* xi_b = sm + OFF_XI + rb * XST;
    const float* xj_b = sm + OFF_XJ + rb * XST;

    // ---- main loop: 64 chunks of K=64 (chunk s == a index s) ----
    #pragma unroll 1
    for (int s = 0; s < 64; ++s) {
        asm volatile("cp.async.wait_group 2;" ::: "memory");
        __syncthreads();

        if (s < 61) {
            const int st = s + 3;
            cp16(wdst + (uint32_t)(st & 3) * STAGE_B + wq * 16, wg + st * 64 + wq * 8);
            cp16(wdst + (uint32_t)(st & 3) * STAGE_B + (wq + 4) * 16, wg + st * 64 + (wq + 4) * 8);
        }
        asm volatile("cp.async.commit_group;" ::: "memory");

        const __half* wsp = (const __half*)((const char*)sm + OFF_WS_B + (s & 3) * STAGE_B);

        float xiv[4];
        #pragma unroll
        for (int m = 0; m < 4; ++m) xiv[m] = xi_b[m * 8 * XST + s];

        #pragma unroll
        for (int j = 0; j < 4; ++j) {               // 4 k-steps of 16
            const int c0 = j * 16 + kq * 2;

            uint32_t ah0[4], ah1[4];
            #pragma unroll
            for (int m = 0; m < 4; ++m) {
                const float2 u = *(const float2*)&xj_b[m * 8 * XST + c0];
                const float2 v = *(const float2*)&xj_b[m * 8 * XST + c0 + 8];
                const __half2 h0 = __floats2half2_rn(xiv[m] * u.x, xiv[m] * u.y);
                const __half2 h1 = __floats2half2_rn(xiv[m] * v.x, xiv[m] * v.y);
                ah0[m] = *(const uint32_t*)&h0;
                ah1[m] = *(const uint32_t*)&h1;
            }

            #pragma unroll
            for (int nt = 0; nt < 4; ++nt) {
                const __half* wr = wsp + (nb + nt * 8) * WROW + c0;
                const uint32_t bb0 = *(const uint32_t*)wr;
                const uint32_t bb1 = *(const uint32_t*)(wr + 8);
                mma16(acc[0][nt], ah0[0], ah0[1], ah1[0], ah1[1], bb0, bb1);
                mma16(acc[1][nt], ah0[2], ah0[3], ah1[2], ah1[3], bb0, bb1);
            }
        }
    }

    // ---- epilogue: bias + store ----
    const int colb = warpN * 32 + kq * 2;
    #pragma unroll
    for (int mt = 0; mt < 2; ++mt) {
        const int r_ = b0 + warpM * 32 + mt * 16 + (lane >> 2);
        float* o0 = out + (size_t)r_ * OUT_ROW + p * 64;
        float* o1 = out + (size_t)(r_ + 8) * OUT_ROW + p * 64;
        #pragma unroll
        for (int nt = 0; nt < 4; ++nt) {
            const int cl = colb + nt * 8;
            const float bz0 = sm[OFF_BIAS + cl];
            const float bz1 = sm[OFF_BIAS + cl + 1];
            float2 v0, v1;
            v0.x = acc[mt][nt][0] + bz0; v0.y = acc[mt][nt][1] + bz1;
            v1.x = acc[mt][nt][2] + bz0; v1.y = acc[mt][nt][3] + bz1;
            *(float2*)(o0 + cl) = v0;
            *(float2*)(o1 + cl) = v1;
        }
    }
}

extern "C" void kernel_launch(void* const* d_in, const int* in_sizes, int n_in,
                              void* d_out, int out_size)
{
    const float* x    = (const float*)d_in[0];   // (1024, 16, 64)
    const float* W    = (const float*)d_in[1];   // (120, 64, 4096)
    const float* bias = (const float*)d_in[2];   // (120, 64)
    float* out = (float*)d_out;                  // (1024, 120, 64)

    // 1) W -> fp16 scratch (31.46M elems / 4 per thread / 256 per block)
    convert_W_kernel<<<WELEMS / (256 * 4), 256>>>(W);

    // 2) main GEMM
    cudaFuncSetAttribute(op_fp16_kernel,
                         cudaFuncAttributeMaxDynamicSharedMemorySize, SM_BYTES);
    op_fp16_kernel<<<PDIM * 8, 256, SM_BYTES>>>(x, bias, out);
}

// round 5
// speedup vs baseline: 6.5588x; 1.6472x over previous
#include <cuda_runtime.h>
#include <cuda_fp16.h>
#include <cstdint>

// B=1024, F=16, D=64, P=120
// out[b,p,k] = sum_{a,c} xi[b,a]*xj[b,c]*W[p,k,a*64+c] + bias[p,k]
// Per (p, b-tile): C[128,64] = Z[128,4096] @ W_p[64,4096]^T via mma.m16n8k16.f16 (f32 acc).
// W pre-converted to fp16 once per launch. Z fragments built in registers from
// half2-resident xj (HMUL2) -- no LDS for A in the hot loop.

#define PDIM 120
#define OUT_ROW (PDIM * 64)
#define WELEMS (120 * 64 * 4096)

__device__ __half d_Wh[WELEMS];   // 62.9 MB fp16 W scratch

// ---- SMEM layout ----
#define XST 68                          // xi/xj row stride (floats)
#define OFF_XI 0
#define OFF_XJ (128 * XST)              // 8704 floats
#define OFF_BIAS (OFF_XJ + 128 * XST)   // 17408 floats
#define OFF_WS_B ((OFF_BIAS + 64) * 4)  // 69888 bytes (16B aligned)
#define WROW 72                         // W stage row stride (halfs): conflict-free b32 reads
#define STAGE_B (64 * WROW * 2)         // 9216 bytes
#define SM_BYTES (OFF_WS_B + 4 * STAGE_B)  // 106752 -> 2 CTAs/SM

__device__ __forceinline__ uint32_t smem_u32(const void* p) {
    uint32_t a;
    asm("{ .reg .u64 t; cvta.to.shared.u64 t, %1; cvt.u32.u64 %0, t; }" : "=r"(a) : "l"(p));
    return a;
}
__device__ __forceinline__ void cp16(uint32_t dst, const void* src) {
    asm volatile("cp.async.cg.shared.global [%0], [%1], 16;" :: "r"(dst), "l"(src));
}
__device__ __forceinline__ void mma16(float* d,
                                      uint32_t a0, uint32_t a1, uint32_t a2, uint32_t a3,
                                      uint32_t b0, uint32_t b1) {
    asm volatile(
        "mma.sync.aligned.m16n8k16.row.col.f32.f16.f16.f32 "
        "{%0,%1,%2,%3},{%4,%5,%6,%7},{%8,%9},{%0,%1,%2,%3};"
        : "+f"(d[0]), "+f"(d[1]), "+f"(d[2]), "+f"(d[3])
        : "r"(a0), "r"(a1), "r"(a2), "r"(a3), "r"(b0), "r"(b1));
}

// ---- W fp32 -> fp16 convert: 31.46M elems, 4 per thread ----
__global__ __launch_bounds__(256)
void convert_W_kernel(const float* __restrict__ W)
{
    const size_t i4 = ((size_t)blockIdx.x * 256 + threadIdx.x) * 4;
    const float4 v = *(const float4*)(W + i4);
    __half2 h0 = __floats2half2_rn(v.x, v.y);
    __half2 h1 = __floats2half2_rn(v.z, v.w);
    uint2 u;
    u.x = *(uint32_t*)&h0;
    u.y = *(uint32_t*)&h1;
    *(uint2*)(&d_Wh[i4]) = u;
}

__global__ __launch_bounds__(256, 2)
void op_fp16_kernel(const float* __restrict__ x,
                    const float* __restrict__ bias,
                    float* __restrict__ out)
{
    extern __shared__ __align__(16) float sm[];
    const int tid  = threadIdx.x;
    const int lane = tid & 31;
    const int wid  = tid >> 5;
    const int warpM = wid & 3;    // 4 x 32 rows = 128 M
    const int warpN = wid >> 2;   // 2 x 32 cols = 64 N
    const int p  = blockIdx.x >> 3;
    const int b0 = (blockIdx.x & 7) << 7;

    // pair (fi, fj) from triu_indices(16, k=1)
    int fi = 0, rem = p;
    while (rem >= 15 - fi) { rem -= 15 - fi; ++fi; }
    const int fj = fi + 1 + rem;

    // ---- one-time fills: xi/xj tiles, bias ----
    {
        const int c4 = (tid & 15) * 4, r0 = tid >> 4;
        #pragma unroll
        for (int it = 0; it < 8; ++it) {
            const int row = r0 + it * 16;
            const float* g = x + (size_t)(b0 + row) * 1024;
            *(float4*)&sm[OFF_XI + row * XST + c4] = *(const float4*)(g + fi * 64 + c4);
            *(float4*)&sm[OFF_XJ + row * XST + c4] = *(const float4*)(g + fj * 64 + c4);
        }
    }
    if (tid < 16)
        *(float4*)&sm[OFF_BIAS + tid * 4] = *(const float4*)(bias + p * 64 + tid * 4);

    const __half* Wp = d_Wh + (size_t)p * (64 * 4096);
    const uint32_t sb = smem_u32(sm);
    const uint32_t wsb = sb + OFF_WS_B;

    // cp.async mapping: row wn = tid>>2 (0..63), two 16B quarters wq, wq+4
    const int wn = tid >> 2, wq = tid & 3;
    const __half* wg = Wp + (size_t)wn * 4096;
    const uint32_t wdst = wsb + (uint32_t)(wn * (WROW * 2));

    // prologue: stages 0..2
    #pragma unroll
    for (int st = 0; st < 3; ++st) {
        cp16(wdst + (uint32_t)st * STAGE_B + wq * 16, wg + st * 64 + wq * 8);
        cp16(wdst + (uint32_t)st * STAGE_B + (wq + 4) * 16, wg + st * 64 + (wq + 4) * 8);
        asm volatile("cp.async.commit_group;" ::: "memory");
    }

    float acc[2][4][4];
    #pragma unroll
    for (int mt = 0; mt < 2; ++mt)
        #pragma unroll
        for (int nt = 0; nt < 4; ++nt)
            #pragma unroll
            for (int q = 0; q < 4; ++q) acc[mt][nt][q] = 0.0f;

    const int rb = warpM * 32 + (lane >> 2);   // A row base (m=0)
    const int nb = warpN * 32 + (lane >> 2);   // B col base (nt=0)
    const int kq = lane & 3;

    const float* xi_b = sm + OFF_XI + rb * XST;
    const float* xj_b = sm + OFF_XJ + rb * XST;

    __syncthreads();  // xi/xj tiles visible

    // ---- xj -> registers as packed half2 (fixed across all chunks) ----
    // xjh[m][2j]   = (xj[row_m][j*16+kq*2],   xj[row_m][j*16+kq*2+1])
    // xjh[m][2j+1] = (xj[row_m][j*16+kq*2+8], xj[row_m][j*16+kq*2+9])
    __half2 xjh[4][8];
    #pragma unroll
    for (int m = 0; m < 4; ++m) {
        const float* xr = xj_b + m * 8 * XST;
        #pragma unroll
        for (int j = 0; j < 4; ++j) {
            const float2 u = *(const float2*)&xr[j * 16 + kq * 2];
            const float2 v = *(const float2*)&xr[j * 16 + kq * 2 + 8];
            xjh[m][2 * j]     = __floats2half2_rn(u.x, u.y);
            xjh[m][2 * j + 1] = __floats2half2_rn(v.x, v.y);
        }
    }

    // ---- main loop: 64 chunks of K=64 (chunk s == a index s) ----
    #pragma unroll 1
    for (int s = 0; s < 64; ++s) {
        asm volatile("cp.async.wait_group 2;" ::: "memory");
        __syncthreads();

        if (s < 61) {
            const int st = s + 3;
            cp16(wdst + (uint32_t)(st & 3) * STAGE_B + wq * 16, wg + st * 64 + wq * 8);
            cp16(wdst + (uint32_t)(st & 3) * STAGE_B + (wq + 4) * 16, wg + st * 64 + (wq + 4) * 8);
        }
        asm volatile("cp.async.commit_group;" ::: "memory");

        const __half* wsp = (const __half*)((const char*)sm + OFF_WS_B + (s & 3) * STAGE_B);

        __half2 xiv[4];
        #pragma unroll
        for (int m = 0; m < 4; ++m)
            xiv[m] = __float2half2_rn(xi_b[m * 8 * XST + s]);

        #pragma unroll
        for (int j = 0; j < 4; ++j) {               // 4 k-steps of 16
            const int c0 = j * 16 + kq * 2;

            uint32_t ah0[4], ah1[4];
            #pragma unroll
            for (int m = 0; m < 4; ++m) {
                const __half2 h0 = __hmul2(xiv[m], xjh[m][2 * j]);
                const __half2 h1 = __hmul2(xiv[m], xjh[m][2 * j + 1]);
                ah0[m] = *(const uint32_t*)&h0;
                ah1[m] = *(const uint32_t*)&h1;
            }

            #pragma unroll
            for (int nt = 0; nt < 4; ++nt) {
                const __half* wr = wsp + (nb + nt * 8) * WROW + c0;
                const uint32_t bb0 = *(const uint32_t*)wr;
                const uint32_t bb1 = *(const uint32_t*)(wr + 8);
                mma16(acc[0][nt], ah0[0], ah0[1], ah1[0], ah1[1], bb0, bb1);
                mma16(acc[1][nt], ah0[2], ah0[3], ah1[2], ah1[3], bb0, bb1);
            }
        }
    }

    // ---- epilogue: bias + store ----
    const int colb = warpN * 32 + kq * 2;
    #pragma unroll
    for (int mt = 0; mt < 2; ++mt) {
        const int r_ = b0 + warpM * 32 + mt * 16 + (lane >> 2);
        float* o0 = out + (size_t)r_ * OUT_ROW + p * 64;
        float* o1 = out + (size_t)(r_ + 8) * OUT_ROW + p * 64;
        #pragma unroll
        for (int nt = 0; nt < 4; ++nt) {
            const int cl = colb + nt * 8;
            const float bz0 = sm[OFF_BIAS + cl];
            const float bz1 = sm[OFF_BIAS + cl + 1];
            float2 v0, v1;
            v0.x = acc[mt][nt][0] + bz0; v0.y = acc[mt][nt][1] + bz1;
            v1.x = acc[mt][nt][2] + bz0; v1.y = acc[mt][nt][3] + bz1;
            *(float2*)(o0 + cl) = v0;
            *(float2*)(o1 + cl) = v1;
        }
    }
}

extern "C" void kernel_launch(void* const* d_in, const int* in_sizes, int n_in,
                              void* d_out, int out_size)
{
    const float* x    = (const float*)d_in[0];   // (1024, 16, 64)
    const float* W    = (const float*)d_in[1];   // (120, 64, 4096)
    const float* bias = (const float*)d_in[2];   // (120, 64)
    float* out = (float*)d_out;                  // (1024, 120, 64)

    // 1) W -> fp16 scratch
    convert_W_kernel<<<WELEMS / (256 * 4), 256>>>(W);

    // 2) main GEMM
    cudaFuncSetAttribute(op_fp16_kernel,
                         cudaFuncAttributeMaxDynamicSharedMemorySize, SM_BYTES);
    op_fp16_kernel<<<PDIM * 8, 256, SM_BYTES>>>(x, bias, out);
}